// round 7
// baseline (speedup 1.0000x reference)
#include <cuda_runtime.h>
#include <math.h>

#define BSZ 4096
#define DIM 128

// Scratch: 64MB similarity matrix (L2 is 126MB -> stays L2-resident),
// plus per-row partial results for a deterministic final reduction.
__device__ float g_S[(size_t)BSZ * BSZ];
__device__ float g_row[BSZ];
__device__ int   g_valid[BSZ];

// ---------------- packed fp32x2 helpers (Blackwell FFMA2) ----------------
__device__ __forceinline__ unsigned long long ffma2(unsigned long long a,
                                                    unsigned long long b,
                                                    unsigned long long c) {
    unsigned long long d;
    asm("fma.rn.f32x2 %0, %1, %2, %3;" : "=l"(d) : "l"(a), "l"(b), "l"(c));
    return d;
}
__device__ __forceinline__ unsigned long long pack2(float lo, float hi) {
    unsigned long long d;
    asm("mov.b64 %0, {%1, %2};" : "=l"(d) : "f"(lo), "f"(hi));
    return d;
}
__device__ __forceinline__ float2 unpack2(unsigned long long v) {
    float2 r;
    asm("mov.b64 {%0, %1}, %2;" : "=f"(r.x), "=f"(r.y) : "l"(v));
    return r;
}

// ---------------- Kernel 1: S = F * F^T (fp32, 128x128 CTA tiles) --------
#define KC 16
#define SROW 132  // padded smem row stride (floats), 16B-aligned, conflict-free

__global__ __launch_bounds__(256) void gemm_kernel(const float* __restrict__ F) {
    __shared__ float As[KC * SROW];
    __shared__ float Bs[KC * SROW];

    const int tid = threadIdx.x;
    const int tx = tid & 15;         // 0..15 -> 8 cols each
    const int ty = tid >> 4;         // 0..15 -> 8 rows each
    const int i0 = blockIdx.y * 128;
    const int j0 = blockIdx.x * 128;

    unsigned long long acc[8][4];
#pragma unroll
    for (int ii = 0; ii < 8; ii++)
#pragma unroll
        for (int p = 0; p < 4; p++) acc[ii][p] = 0ull;

    for (int k0 = 0; k0 < DIM; k0 += KC) {
        __syncthreads();
        // Load A chunk (128 rows x 16 k) and B chunk, 2 float4 each per thread
#pragma unroll
        for (int t = 0; t < 2; t++) {
            int q  = tid + t * 256;      // 0..511
            int r  = q >> 2;             // row within tile 0..127
            int c4 = q & 3;              // which float4 of the 16-k chunk
            float4 av = *(const float4*)(F + (size_t)(i0 + r) * DIM + k0 + c4 * 4);
            As[(c4 * 4 + 0) * SROW + r] = av.x;
            As[(c4 * 4 + 1) * SROW + r] = av.y;
            As[(c4 * 4 + 2) * SROW + r] = av.z;
            As[(c4 * 4 + 3) * SROW + r] = av.w;
            float4 bv = *(const float4*)(F + (size_t)(j0 + r) * DIM + k0 + c4 * 4);
            Bs[(c4 * 4 + 0) * SROW + r] = bv.x;
            Bs[(c4 * 4 + 1) * SROW + r] = bv.y;
            Bs[(c4 * 4 + 2) * SROW + r] = bv.z;
            Bs[(c4 * 4 + 3) * SROW + r] = bv.w;
        }
        __syncthreads();

#pragma unroll
        for (int kk = 0; kk < KC; kk++) {
            float4 a0 = *(const float4*)&As[kk * SROW + ty * 8];
            float4 a1 = *(const float4*)&As[kk * SROW + ty * 8 + 4];
            float4 b0 = *(const float4*)&Bs[kk * SROW + tx * 8];
            float4 b1 = *(const float4*)&Bs[kk * SROW + tx * 8 + 4];
            unsigned long long bp[4];
            bp[0] = pack2(b0.x, b0.y);
            bp[1] = pack2(b0.z, b0.w);
            bp[2] = pack2(b1.x, b1.y);
            bp[3] = pack2(b1.z, b1.w);
            float aa[8] = {a0.x, a0.y, a0.z, a0.w, a1.x, a1.y, a1.z, a1.w};
#pragma unroll
            for (int ii = 0; ii < 8; ii++) {
                unsigned long long ad = pack2(aa[ii], aa[ii]);
#pragma unroll
                for (int p = 0; p < 4; p++) acc[ii][p] = ffma2(ad, bp[p], acc[ii][p]);
            }
        }
    }

    // Epilogue: coalesced float2 stores
#pragma unroll
    for (int ii = 0; ii < 8; ii++) {
        size_t base = (size_t)(i0 + ty * 8 + ii) * BSZ + j0 + tx * 8;
#pragma unroll
        for (int p = 0; p < 4; p++) {
            *(float2*)(g_S + base + 2 * p) = unpack2(acc[ii][p]);
        }
    }
}

// ---------------- Kernel 2: per-row stats + exact top-200 radix select ----
__device__ __forceinline__ float key2f(unsigned int k) {
    unsigned int u = (k & 0x80000000u) ? (k ^ 0x80000000u) : ~k;
    return __uint_as_float(u);
}

__global__ __launch_bounds__(256) void row_kernel(const int* __restrict__ labels) {
    __shared__ unsigned int key[BSZ];   // monotone-mapped similarity keys
    __shared__ float rf[256];
    __shared__ int   ri[256];
    __shared__ int   hist[256];
    __shared__ unsigned int s_sel;      // selected bucket
    __shared__ int s_krem;              // remaining k within selected bucket

    const int tid = threadIdx.x;
    const int i = blockIdx.x;
    const int labi = labels[i];
    const float* srow = g_S + (size_t)i * BSZ;

    // --- load row, build keys, local max (max over ALL j, incl. diagonal) ---
    float mx = -1e30f;
#pragma unroll
    for (int t = 0; t < 4; t++) {
        int j4 = tid + t * 256;                       // float4 index 0..1023
        float4 v = ((const float4*)srow)[j4];
        float vs[4] = {v.x, v.y, v.z, v.w};
#pragma unroll
        for (int e = 0; e < 4; e++) {
            float f = vs[e];
            mx = fmaxf(mx, f);
            unsigned int u = __float_as_uint(f);
            key[j4 * 4 + e] = (u & 0x80000000u) ? ~u : (u | 0x80000000u);
        }
    }
    rf[tid] = mx;
    __syncthreads();
    for (int s = 128; s; s >>= 1) {
        if (tid < s) rf[tid] = fmaxf(rf[tid], rf[tid + s]);
        __syncthreads();
    }
    const float smax = rf[0];
    __syncthreads();

    // --- positives pass: sums + zero out same-class keys (incl. diagonal) ---
    float sl = 0.f, se = 0.f;
    int cnt = 0;
#pragma unroll
    for (int t = 0; t < 16; t++) {
        int j = tid + t * 256;
        if (labels[j] == labi) {
            if (j != i) {
                float s = key2f(key[j]);
                float lg = (s - smax) * 10.f;
                sl += lg;
                se += expf(lg);
                cnt++;
            }
            key[j] = 0u;   // exclude positives + self from top-k candidates
        }
    }
    // reduce sl
    rf[tid] = sl; __syncthreads();
    for (int s = 128; s; s >>= 1) { if (tid < s) rf[tid] += rf[tid + s]; __syncthreads(); }
    const float sl_tot = rf[0]; __syncthreads();
    // reduce se
    rf[tid] = se; __syncthreads();
    for (int s = 128; s; s >>= 1) { if (tid < s) rf[tid] += rf[tid + s]; __syncthreads(); }
    const float se_tot = rf[0]; __syncthreads();
    // reduce cnt
    ri[tid] = cnt; __syncthreads();
    for (int s = 128; s; s >>= 1) { if (tid < s) ri[tid] += ri[tid + s]; __syncthreads(); }
    const int cnt_tot = ri[0]; __syncthreads();

    // --- 4-pass radix select: exact 200th-largest key among negatives ---
    unsigned int prefix = 0;
    int krem = 200;
    for (int pass = 0; pass < 4; pass++) {
        const int shift = 24 - 8 * pass;
        const unsigned int maskHi = (pass == 0) ? 0u : (0xFFFFFFFFu << (shift + 8));
        hist[tid] = 0;
        __syncthreads();
#pragma unroll
        for (int t = 0; t < 16; t++) {
            unsigned int u = key[tid + t * 256];
            if (((u ^ prefix) & maskHi) == 0u)
                atomicAdd(&hist[(u >> shift) & 255], 1);
        }
        __syncthreads();
        // inclusive suffix-sum of hist: ri[b] = count of candidates in buckets >= b
        ri[tid] = hist[tid];
        __syncthreads();
        for (int off = 1; off < 256; off <<= 1) {
            int v = ri[tid];
            if (tid + off < 256) v += ri[tid + off];
            __syncthreads();
            ri[tid] = v;
            __syncthreads();
        }
        int above = (tid < 255) ? ri[tid + 1] : 0;   // strictly above this bucket
        if (ri[tid] >= krem && above < krem) {       // unique bucket
            s_sel = (unsigned int)tid;
            s_krem = krem - above;
        }
        __syncthreads();
        prefix |= s_sel << shift;
        krem = s_krem;
        __syncthreads();
    }
    const unsigned int pivot = prefix;

    // --- sum exp over top-200 negatives: strictly > pivot, plus krem at pivot ---
    float sg = 0.f;
#pragma unroll
    for (int t = 0; t < 16; t++) {
        unsigned int u = key[tid + t * 256];
        if (u > pivot) sg += expf((key2f(u) - smax) * 10.f);
    }
    rf[tid] = sg; __syncthreads();
    for (int s = 128; s; s >>= 1) { if (tid < s) rf[tid] += rf[tid + s]; __syncthreads(); }

    if (tid == 0) {
        float sg_tot = rf[0] + (float)krem * expf((key2f(pivot) - smax) * 10.f);
        float denom = se_tot + sg_tot;
        bool valid = (labi > 0) && (cnt_tot > 0);
        float per = 0.f;
        if (valid) per = -2.f * (sl_tot / (float)cnt_tot - logf(denom));
        g_row[i] = per;
        g_valid[i] = valid ? 1 : 0;
    }
}

// ---------------- Kernel 3: deterministic final reduction -----------------
__global__ __launch_bounds__(256) void finalize_kernel(float* __restrict__ out) {
    __shared__ float rf[256];
    __shared__ int   ri[256];
    const int tid = threadIdx.x;
    float s = 0.f;
    int c = 0;
    for (int j = tid; j < BSZ; j += 256) {
        s += g_row[j];
        c += g_valid[j];
    }
    rf[tid] = s; ri[tid] = c;
    __syncthreads();
    for (int k = 128; k; k >>= 1) {
        if (tid < k) { rf[tid] += rf[tid + k]; ri[tid] += ri[tid + k]; }
        __syncthreads();
    }
    if (tid == 0) out[0] = rf[0] / (float)ri[0];
}

// --------------------------------------------------------------------------
extern "C" void kernel_launch(void* const* d_in, const int* in_sizes, int n_in,
                              void* d_out, int out_size) {
    const float* F = (const float*)d_in[0];       // [4096, 1, 128] fp32
    const int* labels = (const int*)d_in[1];      // [4096] int32
    (void)in_sizes; (void)n_in; (void)out_size;

    dim3 g1(BSZ / 128, BSZ / 128);
    gemm_kernel<<<g1, 256>>>(F);
    row_kernel<<<BSZ, 256>>>(labels);
    finalize_kernel<<<1, 256>>>((float*)d_out);
}